// round 5
// baseline (speedup 1.0000x reference)
#include <cuda_runtime.h>
#include <math.h>

#define Bb   4
#define Nn   1024
#define Dd   512
#define Hh   8
#define DHh  64
#define HIDn 32

// Static scratch (allocation-free per harness rules)
__device__ float g_q[Bb*Hh*Nn*DHh];
__device__ float g_k[Bb*Hh*Nn*DHh];
__device__ float g_v[Bb*Hh*Nn*DHh];
__device__ float g_logits[(size_t)Bb*Hh*Nn*Nn];   // [B,H,N,N] bias -> logits -> attn (in place)
__device__ float g_att[Bb*Nn*Dd];                 // [B,N,D] attention output

// ---------------------------------------------------------------------------
// Shared GEMM building blocks: 64x64 C tile, 256 threads, 4x4 per thread.
// SMEM tiles stored [k][m]/[k][n] with row pitch 68 (16B-aligned, low conflict)
// so the inner loop uses two LDS.128 per k-step.
// ---------------------------------------------------------------------------

// Load 64x64 tile from row-major src (first index = rows) TRANSPOSED:
// dst[k][m] = src[m*ld + k]
__device__ __forceinline__ void load_tile_T(float (*dst)[68], const float* __restrict__ src,
                                            int ld, int tid) {
    int r  = tid >> 4;
    int c4 = (tid & 15) << 2;
    #pragma unroll
    for (int rr = r; rr < 64; rr += 16) {
        float4 v = *(const float4*)(src + rr * ld + c4);
        dst[c4 + 0][rr] = v.x;
        dst[c4 + 1][rr] = v.y;
        dst[c4 + 2][rr] = v.z;
        dst[c4 + 3][rr] = v.w;
    }
}

// Load 64x64 tile from row-major src as-is: dst[r][c] = src[r*ld + c]
__device__ __forceinline__ void load_tile_N(float (*dst)[68], const float* __restrict__ src,
                                            int ld, int tid) {
    int r  = tid >> 4;
    int c4 = (tid & 15) << 2;
    #pragma unroll
    for (int rr = r; rr < 64; rr += 16) {
        float4 v = *(const float4*)(src + rr * ld + c4);
        *(float4*)&dst[rr][c4] = v;
    }
}

__device__ __forceinline__ void mm64(float (*As)[68], float (*Bs)[68],
                                     float acc[4][4], int tx, int ty) {
    #pragma unroll
    for (int k = 0; k < 64; k++) {
        float4 a4 = *(const float4*)&As[k][ty << 2];
        float4 b4 = *(const float4*)&Bs[k][tx << 2];
        float a[4] = {a4.x, a4.y, a4.z, a4.w};
        float b[4] = {b4.x, b4.y, b4.z, b4.w};
        #pragma unroll
        for (int i = 0; i < 4; i++)
            #pragma unroll
            for (int j = 0; j < 4; j++)
                acc[i][j] = fmaf(a[i], b[j], acc[i][j]);
    }
}

// ---------------------------------------------------------------------------
// K1: QKV projection. C[4096,1536] = x[4096,512] @ qkv_w[512,1536]
// scattered into g_q/g_k/g_v as [B,H,N,dh].
// ---------------------------------------------------------------------------
__global__ __launch_bounds__(256) void k_qkv(const float* __restrict__ X,
                                             const float* __restrict__ W) {
    __shared__ float As[64][68];
    __shared__ float Bs[64][68];
    int tid = threadIdx.x, tx = tid & 15, ty = tid >> 4;
    int m0 = blockIdx.y << 6, n0 = blockIdx.x << 6;
    float acc[4][4] = {};
    for (int k0 = 0; k0 < Dd; k0 += 64) {
        load_tile_T(As, X + (size_t)m0 * Dd + k0, Dd, tid);
        load_tile_N(Bs, W + (size_t)k0 * (3 * Dd) + n0, 3 * Dd, tid);
        __syncthreads();
        mm64(As, Bs, acc, tx, ty);
        __syncthreads();
    }
    #pragma unroll
    for (int i = 0; i < 4; i++) {
        int r = m0 + (ty << 2) + i;
        int b = r >> 10, n = r & 1023;
        #pragma unroll
        for (int j = 0; j < 4; j++) {
            int c   = n0 + (tx << 2) + j;
            int sec = c >> 9;       // 0=q,1=k,2=v
            int d0  = c & 511;
            int h   = d0 >> 6, e = d0 & 63;
            float* dst = (sec == 0) ? g_q : (sec == 1) ? g_k : g_v;
            dst[((size_t)(b * Hh + h) * Nn + n) * DHh + e] = acc[i][j];
        }
    }
}

// ---------------------------------------------------------------------------
// K2: relative-position bias MLP, computed ONCE per (b,i,j) pair for all 8
// heads, written into g_logits[b,h,i,j].
// ---------------------------------------------------------------------------
__global__ __launch_bounds__(256) void k_bias(const float* __restrict__ coords,
                                              const float* __restrict__ w1,
                                              const float* __restrict__ b1,
                                              const float* __restrict__ w2,
                                              const float* __restrict__ b2) {
    __shared__ float sw1[3 * HIDn];
    __shared__ float sb1[HIDn];
    __shared__ float sw2[HIDn * Hh];
    __shared__ float sb2[Hh];
    __shared__ float ci[32][3];
    __shared__ float cj[32][3];

    int b  = blockIdx.z;
    int i0 = blockIdx.y << 5;
    int j0 = blockIdx.x << 5;
    int tid = threadIdx.x;

    if (tid < 96)  sw1[tid] = w1[tid];
    if (tid < 32)  sb1[tid] = b1[tid];
    if (tid < 256) sw2[tid] = w2[tid];
    if (tid < 8)   sb2[tid] = b2[tid];
    if (tid < 96) {
        int r = tid / 3, c = tid % 3;
        ci[r][c] = coords[((size_t)(b << 10) + i0 + r) * 3 + c];
    }
    if (tid >= 128 && tid < 224) {
        int t = tid - 128;
        int r = t / 3, c = t % 3;
        cj[r][c] = coords[((size_t)(b << 10) + j0 + r) * 3 + c];
    }
    __syncthreads();

    for (int p = tid; p < 1024; p += 256) {
        int i = p >> 5, j = p & 31;
        float dx = ci[i][0] - cj[j][0];
        float dy = ci[i][1] - cj[j][1];
        float dz = ci[i][2] - cj[j][2];
        float acc[Hh];
        #pragma unroll
        for (int h = 0; h < Hh; h++) acc[h] = sb2[h];
        #pragma unroll
        for (int m = 0; m < HIDn; m++) {
            float hs = fmaf(dx, sw1[m], fmaf(dy, sw1[32 + m], fmaf(dz, sw1[64 + m], sb1[m])));
            float g  = 0.5f * hs * (1.0f + erff(hs * 0.70710678118654752f));  // exact GELU
            #pragma unroll
            for (int h = 0; h < Hh; h++) acc[h] = fmaf(g, sw2[m * Hh + h], acc[h]);
        }
        int gi = i0 + i, gj = j0 + j;
        #pragma unroll
        for (int h = 0; h < Hh; h++)
            g_logits[((size_t)((b * Hh + h) << 10) + gi) * Nn + gj] = acc[h];
    }
}

// ---------------------------------------------------------------------------
// K3: dots. logits[b,h,i,j] += scale * (q_i . k_j)   (A @ B^T, k-dim = dh = 64)
// ---------------------------------------------------------------------------
__global__ __launch_bounds__(256) void k_dots() {
    __shared__ float As[64][68];
    __shared__ float Bs[64][68];
    int tid = threadIdx.x, tx = tid & 15, ty = tid >> 4;
    int bh = blockIdx.z;
    int i0 = blockIdx.y << 6, j0 = blockIdx.x << 6;

    const float* Q = g_q + (size_t)bh * Nn * DHh;
    const float* K = g_k + (size_t)bh * Nn * DHh;
    float* C = g_logits + (size_t)bh * Nn * Nn;

    float acc[4][4] = {};
    load_tile_T(As, Q + (size_t)i0 * DHh, DHh, tid);  // As[k][m] = Q[i][k]
    load_tile_T(Bs, K + (size_t)j0 * DHh, DHh, tid);  // Bs[k][n] = K[j][k]
    __syncthreads();
    mm64(As, Bs, acc, tx, ty);

    const float scale = 0.125f;  // 64^-0.5
    #pragma unroll
    for (int i = 0; i < 4; i++) {
        int gi = i0 + (ty << 2) + i;
        #pragma unroll
        for (int j = 0; j < 4; j++) {
            int gj = j0 + (tx << 2) + j;
            size_t idx = (size_t)gi * Nn + gj;
            C[idx] = fmaf(acc[i][j], scale, C[idx]);
        }
    }
}

// ---------------------------------------------------------------------------
// K4: row softmax over j (in place), with key padding mask applied.
// ---------------------------------------------------------------------------
__global__ __launch_bounds__(256) void k_softmax(const unsigned char* __restrict__ mask) {
    int row = blockIdx.x;          // (b*H + h)*N + i
    int b   = row >> 13;           // / (H*N)
    float* p = g_logits + (size_t)row * Nn;
    const unsigned char* mrow = mask + ((size_t)b << 10);
    int tid = threadIdx.x;

    float vals[4];
    float mx = -1e30f;
    #pragma unroll
    for (int q = 0; q < 4; q++) {
        int j = tid + (q << 8);
        float v = p[j];
        if (mrow[j]) v = -1e30f;
        vals[q] = v;
        mx = fmaxf(mx, v);
    }
    __shared__ float red[256];
    red[tid] = mx;
    __syncthreads();
    #pragma unroll
    for (int s = 128; s > 0; s >>= 1) {
        if (tid < s) red[tid] = fmaxf(red[tid], red[tid + s]);
        __syncthreads();
    }
    mx = red[0];
    __syncthreads();

    float sum = 0.0f;
    #pragma unroll
    for (int q = 0; q < 4; q++) {
        vals[q] = __expf(vals[q] - mx);
        sum += vals[q];
    }
    red[tid] = sum;
    __syncthreads();
    #pragma unroll
    for (int s = 128; s > 0; s >>= 1) {
        if (tid < s) red[tid] += red[tid + s];
        __syncthreads();
    }
    float inv = 1.0f / red[0];
    #pragma unroll
    for (int q = 0; q < 4; q++)
        p[tid + (q << 8)] = vals[q] * inv;
}

// ---------------------------------------------------------------------------
// K5: out_h = attn @ V, per (b,h). C[1024,64] = A[1024,1024] @ V[1024,64],
// written to g_att as [B,N,H*dh].
// ---------------------------------------------------------------------------
__global__ __launch_bounds__(256) void k_av() {
    __shared__ float As[64][68];
    __shared__ float Bs[64][68];
    int tid = threadIdx.x, tx = tid & 15, ty = tid >> 4;
    int bh = blockIdx.y;
    int i0 = blockIdx.x << 6;

    const float* Am = g_logits + (size_t)bh * Nn * Nn;
    const float* Vm = g_v + (size_t)bh * Nn * DHh;

    float acc[4][4] = {};
    for (int k0 = 0; k0 < Nn; k0 += 64) {
        load_tile_T(As, Am + (size_t)i0 * Nn + k0, Nn, tid);
        load_tile_N(Bs, Vm + (size_t)k0 * DHh, DHh, tid);
        __syncthreads();
        mm64(As, Bs, acc, tx, ty);
        __syncthreads();
    }
    int b = bh >> 3, h = bh & 7;
    #pragma unroll
    for (int i = 0; i < 4; i++) {
        int gi = i0 + (ty << 2) + i;
        #pragma unroll
        for (int j = 0; j < 4; j++) {
            int e = (tx << 2) + j;
            g_att[((size_t)(b << 10) + gi) * Dd + h * DHh + e] = acc[i][j];
        }
    }
}

// ---------------------------------------------------------------------------
// K6: output projection. out[4096,512] = g_att @ out_w + out_b
// ---------------------------------------------------------------------------
__global__ __launch_bounds__(256) void k_out(const float* __restrict__ W,
                                             const float* __restrict__ bias,
                                             float* __restrict__ out) {
    __shared__ float As[64][68];
    __shared__ float Bs[64][68];
    int tid = threadIdx.x, tx = tid & 15, ty = tid >> 4;
    int m0 = blockIdx.y << 6, n0 = blockIdx.x << 6;

    float acc[4][4] = {};
    for (int k0 = 0; k0 < Dd; k0 += 64) {
        load_tile_T(As, g_att + (size_t)m0 * Dd + k0, Dd, tid);
        load_tile_N(Bs, W + (size_t)k0 * Dd + n0, Dd, tid);
        __syncthreads();
        mm64(As, Bs, acc, tx, ty);
        __syncthreads();
    }
    #pragma unroll
    for (int i = 0; i < 4; i++) {
        int r = m0 + (ty << 2) + i;
        #pragma unroll
        for (int j = 0; j < 4; j++) {
            int c = n0 + (tx << 2) + j;
            out[(size_t)r * Dd + c] = acc[i][j] + __ldg(&bias[c]);
        }
    }
}

// ---------------------------------------------------------------------------
// Launch
// ---------------------------------------------------------------------------
extern "C" void kernel_launch(void* const* d_in, const int* in_sizes, int n_in,
                              void* d_out, int out_size) {
    const float*         x      = (const float*)d_in[0];
    const float*         coords = (const float*)d_in[1];
    const unsigned char* mask   = (const unsigned char*)d_in[2];
    const float*         qkv_w  = (const float*)d_in[3];
    const float*         out_w  = (const float*)d_in[4];
    const float*         out_b  = (const float*)d_in[5];
    const float*         w1     = (const float*)d_in[6];
    const float*         b1     = (const float*)d_in[7];
    const float*         w2     = (const float*)d_in[8];
    const float*         b2     = (const float*)d_in[9];
    float*               out    = (float*)d_out;

    k_qkv    <<<dim3(24, 64),      256>>>(x, qkv_w);
    k_bias   <<<dim3(32, 32, Bb),  256>>>(coords, w1, b1, w2, b2);
    k_dots   <<<dim3(16, 16, 32),  256>>>();
    k_softmax<<<Bb * Hh * Nn,      256>>>(mask);
    k_av     <<<dim3(16, 32),      256>>>();
    k_out    <<<dim3(8, 64),       256>>>(out_w, out_b, out);
}

// round 6
// speedup vs baseline: 1.2343x; 1.2343x over previous
#include <cuda_runtime.h>
#include <math.h>

#define Bb   4
#define Nn   1024
#define Dd   512
#define Hh   8
#define DHh  64
#define HIDn 32
#define BKk  16

// Static scratch (allocation-free per harness rules)
__device__ float g_q[Bb*Hh*Nn*DHh];               // pre-scaled by dh^-0.5
__device__ float g_k[Bb*Hh*Nn*DHh];
__device__ float g_v[Bb*Hh*Nn*DHh];
__device__ float g_logits[(size_t)Bb*Hh*Nn*Nn];   // bias -> logits -> attn (in place)
__device__ float g_att[Bb*Nn*Dd];                 // [B,N,D] attention output

// ---------------------------------------------------------------------------
// SMEM tile loaders (256 threads). Pitches padded (+4) and 16B-aligned.
// ---------------------------------------------------------------------------

// dst[k][m] = src[m*ld + k], tile 128(m) x 16(k). src row-major [M][K].
__device__ __forceinline__ void load_T128(float* dst, const float* __restrict__ src,
                                          int ld, int tid) {
    #pragma unroll
    for (int it = 0; it < 2; it++) {
        int lin = tid + (it << 8);
        int m   = lin >> 2;
        int kq  = (lin & 3) << 2;
        float4 v = *(const float4*)(src + (size_t)m * ld + kq);
        dst[(kq + 0) * 132 + m] = v.x;
        dst[(kq + 1) * 132 + m] = v.y;
        dst[(kq + 2) * 132 + m] = v.z;
        dst[(kq + 3) * 132 + m] = v.w;
    }
}

// dst[k][n] = src[k*ld + n], tile 16(k) x 128(n). src row-major [K][N].
__device__ __forceinline__ void load_N128(float* dst, const float* __restrict__ src,
                                          int ld, int tid) {
    #pragma unroll
    for (int it = 0; it < 2; it++) {
        int lin = tid + (it << 8);
        int k   = lin >> 5;
        int nq  = (lin & 31) << 2;
        *(float4*)(dst + k * 132 + nq) = *(const float4*)(src + (size_t)k * ld + nq);
    }
}

// dst[k][n] = src[k*ld + n], tile 16(k) x 64(n).
__device__ __forceinline__ void load_N64(float* dst, const float* __restrict__ src,
                                         int ld, int tid) {
    int k  = tid >> 4;
    int nq = (tid & 15) << 2;
    *(float4*)(dst + k * 68 + nq) = *(const float4*)(src + (size_t)k * ld + nq);
}

// 16 k-steps of 8x8 microtile FFMA
__device__ __forceinline__ void mm8x8(const float* As, const float* Bs,
                                      float acc[8][8], int tx, int ty) {
    #pragma unroll
    for (int k = 0; k < BKk; k++) {
        float a[8], b[8];
        *(float4*)&a[0] = *(const float4*)(As + k * 132 + (ty << 3));
        *(float4*)&a[4] = *(const float4*)(As + k * 132 + (ty << 3) + 4);
        *(float4*)&b[0] = *(const float4*)(Bs + k * 132 + (tx << 3));
        *(float4*)&b[4] = *(const float4*)(Bs + k * 132 + (tx << 3) + 4);
        #pragma unroll
        for (int i = 0; i < 8; i++)
            #pragma unroll
            for (int j = 0; j < 8; j++)
                acc[i][j] = fmaf(a[i], b[j], acc[i][j]);
    }
}

// 16 k-steps of 8x4 microtile FFMA (BN=64)
__device__ __forceinline__ void mm8x4(const float* As, const float* Bs,
                                      float acc[8][4], int tx, int ty) {
    #pragma unroll
    for (int k = 0; k < BKk; k++) {
        float a[8], b[4];
        *(float4*)&a[0] = *(const float4*)(As + k * 132 + (ty << 3));
        *(float4*)&a[4] = *(const float4*)(As + k * 132 + (ty << 3) + 4);
        *(float4*)&b[0] = *(const float4*)(Bs + k * 68 + (tx << 2));
        #pragma unroll
        for (int i = 0; i < 8; i++)
            #pragma unroll
            for (int j = 0; j < 4; j++)
                acc[i][j] = fmaf(a[i], b[j], acc[i][j]);
    }
}

// ---------------------------------------------------------------------------
// K1: QKV projection. [4096,1536] = x[4096,512] @ qkv_w[512,1536],
// scattered into g_q (scaled by 0.125), g_k, g_v as [B,H,N,dh].
// ---------------------------------------------------------------------------
__global__ __launch_bounds__(256, 2) void k_qkv(const float* __restrict__ X,
                                                const float* __restrict__ W) {
    __shared__ float As[BKk * 132];
    __shared__ float Bs[BKk * 132];
    int tid = threadIdx.x, tx = tid & 15, ty = tid >> 4;
    int n0 = blockIdx.x << 7, m0 = blockIdx.y << 7;
    float acc[8][8] = {};
    for (int k0 = 0; k0 < Dd; k0 += BKk) {
        load_T128(As, X + (size_t)m0 * Dd + k0, Dd, tid);
        load_N128(Bs, W + (size_t)k0 * (3 * Dd) + n0, 3 * Dd, tid);
        __syncthreads();
        mm8x8(As, Bs, acc, tx, ty);
        __syncthreads();
    }
    int c0  = n0 + (tx << 3);
    int sec = c0 >> 9;                 // 0=q,1=k,2=v (8-col block never crosses)
    int d0  = c0 & 511;
    int h   = d0 >> 6, e = d0 & 63;    // never crosses a head boundary
    float* dst = (sec == 0) ? g_q : (sec == 1) ? g_k : g_v;
    float  s   = (sec == 0) ? 0.125f : 1.0f;   // fold dh^-0.5 into q
    #pragma unroll
    for (int i = 0; i < 8; i++) {
        int r = m0 + (ty << 3) + i;
        int b = r >> 10, n = r & 1023;
        float* pd = dst + ((size_t)(b * Hh + h) * Nn + n) * DHh + e;
        *(float4*)pd       = make_float4(acc[i][0]*s, acc[i][1]*s, acc[i][2]*s, acc[i][3]*s);
        *(float4*)(pd + 4) = make_float4(acc[i][4]*s, acc[i][5]*s, acc[i][6]*s, acc[i][7]*s);
    }
}

// ---------------------------------------------------------------------------
// K2: relative-position bias MLP, once per (b,i,j) for all 8 heads.
// ---------------------------------------------------------------------------
__global__ __launch_bounds__(256) void k_bias(const float* __restrict__ coords,
                                              const float* __restrict__ w1,
                                              const float* __restrict__ b1,
                                              const float* __restrict__ w2,
                                              const float* __restrict__ b2) {
    __shared__ float sw1[3 * HIDn];
    __shared__ float sb1[HIDn];
    __shared__ float sw2[HIDn * Hh];
    __shared__ float sb2[Hh];
    __shared__ float ci[32][3];
    __shared__ float cj[32][3];

    int b  = blockIdx.z;
    int i0 = blockIdx.y << 5;
    int j0 = blockIdx.x << 5;
    int tid = threadIdx.x;

    if (tid < 96)  sw1[tid] = w1[tid];
    if (tid < 32)  sb1[tid] = b1[tid];
    sw2[tid] = w2[tid];
    if (tid < 8)   sb2[tid] = b2[tid];
    if (tid < 96) {
        int r = tid / 3, c = tid % 3;
        ci[r][c] = coords[((size_t)(b << 10) + i0 + r) * 3 + c];
    }
    if (tid >= 128 && tid < 224) {
        int t = tid - 128;
        int r = t / 3, c = t % 3;
        cj[r][c] = coords[((size_t)(b << 10) + j0 + r) * 3 + c];
    }
    __syncthreads();

    for (int p = tid; p < 1024; p += 256) {
        int i = p >> 5, j = p & 31;
        float dx = ci[i][0] - cj[j][0];
        float dy = ci[i][1] - cj[j][1];
        float dz = ci[i][2] - cj[j][2];
        float acc[Hh];
        #pragma unroll
        for (int h = 0; h < Hh; h++) acc[h] = sb2[h];
        #pragma unroll
        for (int m = 0; m < HIDn; m++) {
            float hs = fmaf(dx, sw1[m], fmaf(dy, sw1[32 + m], fmaf(dz, sw1[64 + m], sb1[m])));
            float g  = 0.5f * hs * (1.0f + erff(hs * 0.70710678118654752f));
            #pragma unroll
            for (int h = 0; h < Hh; h++) acc[h] = fmaf(g, sw2[m * Hh + h], acc[h]);
        }
        int gi = i0 + i, gj = j0 + j;
        #pragma unroll
        for (int h = 0; h < Hh; h++)
            g_logits[((size_t)((b * Hh + h) << 10) + gi) * Nn + gj] = acc[h];
    }
}

// ---------------------------------------------------------------------------
// K3: logits[b,h,i,j] += q_i . k_j   (q pre-scaled; A @ B^T with K=64)
// ---------------------------------------------------------------------------
__global__ __launch_bounds__(256, 2) void k_dots() {
    __shared__ float As[BKk * 132];
    __shared__ float Bs[BKk * 132];
    int tid = threadIdx.x, tx = tid & 15, ty = tid >> 4;
    int bh = blockIdx.z;
    int j0 = blockIdx.x << 7, i0 = blockIdx.y << 7;

    const float* Q = g_q + (size_t)bh * Nn * DHh;
    const float* K = g_k + (size_t)bh * Nn * DHh;
    float* C = g_logits + (size_t)bh * Nn * Nn;

    float acc[8][8] = {};
    for (int k0 = 0; k0 < DHh; k0 += BKk) {
        load_T128(As, Q + (size_t)i0 * DHh + k0, DHh, tid);
        load_T128(Bs, K + (size_t)j0 * DHh + k0, DHh, tid);
        __syncthreads();
        mm8x8(As, Bs, acc, tx, ty);
        __syncthreads();
    }
    #pragma unroll
    for (int i = 0; i < 8; i++) {
        int gi = i0 + (ty << 3) + i;
        float* pc = C + (size_t)gi * Nn + j0 + (tx << 3);
        float4 c0 = *(float4*)pc;
        float4 c1 = *(float4*)(pc + 4);
        c0.x += acc[i][0]; c0.y += acc[i][1]; c0.z += acc[i][2]; c0.w += acc[i][3];
        c1.x += acc[i][4]; c1.y += acc[i][5]; c1.z += acc[i][6]; c1.w += acc[i][7];
        *(float4*)pc       = c0;
        *(float4*)(pc + 4) = c1;
    }
}

// ---------------------------------------------------------------------------
// K4: row softmax over j (in place), key-padding mask applied.
// One float4 per thread covers the 1024-row exactly; shuffle reductions.
// ---------------------------------------------------------------------------
__global__ __launch_bounds__(256) void k_softmax(const unsigned char* __restrict__ mask) {
    int row = blockIdx.x;              // (b*H + h)*N + i
    int b   = row >> 13;
    float* p = g_logits + (size_t)row * Nn;
    int tid = threadIdx.x;

    float4 v  = ((const float4*)p)[tid];
    uchar4 mk = ((const uchar4*)(mask + ((size_t)b << 10)))[tid];
    if (mk.x) v.x = -1e30f;
    if (mk.y) v.y = -1e30f;
    if (mk.z) v.z = -1e30f;
    if (mk.w) v.w = -1e30f;

    float mx = fmaxf(fmaxf(v.x, v.y), fmaxf(v.z, v.w));
    #pragma unroll
    for (int o = 16; o; o >>= 1) mx = fmaxf(mx, __shfl_xor_sync(0xFFFFFFFFu, mx, o));
    __shared__ float sm[8];
    __shared__ float ss[8];
    int w = tid >> 5, l = tid & 31;
    if (l == 0) sm[w] = mx;
    __syncthreads();
    mx = fmaxf(fmaxf(fmaxf(sm[0], sm[1]), fmaxf(sm[2], sm[3])),
               fmaxf(fmaxf(sm[4], sm[5]), fmaxf(sm[6], sm[7])));

    v.x = __expf(v.x - mx);
    v.y = __expf(v.y - mx);
    v.z = __expf(v.z - mx);
    v.w = __expf(v.w - mx);
    float sum = v.x + v.y + v.z + v.w;
    #pragma unroll
    for (int o = 16; o; o >>= 1) sum += __shfl_xor_sync(0xFFFFFFFFu, sum, o);
    if (l == 0) ss[w] = sum;
    __syncthreads();
    float tot = (ss[0] + ss[1]) + (ss[2] + ss[3]) + (ss[4] + ss[5]) + (ss[6] + ss[7]);
    float inv = __frcp_rn(tot);

    v.x *= inv; v.y *= inv; v.z *= inv; v.w *= inv;
    ((float4*)p)[tid] = v;
}

// ---------------------------------------------------------------------------
// K5: out_h = attn @ V per (b,h): [1024,64] = [1024,1024] @ [1024,64]
// ---------------------------------------------------------------------------
__global__ __launch_bounds__(256, 2) void k_av() {
    __shared__ float As[BKk * 132];
    __shared__ float Bs[BKk * 68];
    int tid = threadIdx.x, tx = tid & 15, ty = tid >> 4;
    int bh = blockIdx.y;
    int i0 = blockIdx.x << 7;

    const float* Am = g_logits + (size_t)bh * Nn * Nn;
    const float* Vm = g_v + (size_t)bh * Nn * DHh;

    float acc[8][4] = {};
    for (int k0 = 0; k0 < Nn; k0 += BKk) {
        load_T128(As, Am + (size_t)i0 * Nn + k0, Nn, tid);
        load_N64(Bs, Vm + (size_t)k0 * DHh, DHh, tid);
        __syncthreads();
        mm8x4(As, Bs, acc, tx, ty);
        __syncthreads();
    }
    int b = bh >> 3, h = bh & 7;
    #pragma unroll
    for (int i = 0; i < 8; i++) {
        int gi = i0 + (ty << 3) + i;
        float* pd = g_att + ((size_t)(b << 10) + gi) * Dd + h * DHh + (tx << 2);
        *(float4*)pd = make_float4(acc[i][0], acc[i][1], acc[i][2], acc[i][3]);
    }
}

// ---------------------------------------------------------------------------
// K6: output projection. out[4096,512] = g_att @ out_w + out_b
// ---------------------------------------------------------------------------
__global__ __launch_bounds__(256, 2) void k_out(const float* __restrict__ W,
                                                const float* __restrict__ bias,
                                                float* __restrict__ out) {
    __shared__ float As[BKk * 132];
    __shared__ float Bs[BKk * 68];
    int tid = threadIdx.x, tx = tid & 15, ty = tid >> 4;
    int n0 = blockIdx.x << 6, m0 = blockIdx.y << 7;

    float acc[8][4] = {};
    for (int k0 = 0; k0 < Dd; k0 += BKk) {
        load_T128(As, g_att + (size_t)m0 * Dd + k0, Dd, tid);
        load_N64(Bs, W + (size_t)k0 * Dd + n0, Dd, tid);
        __syncthreads();
        mm8x4(As, Bs, acc, tx, ty);
        __syncthreads();
    }
    float4 bv = *(const float4*)(bias + n0 + (tx << 2));
    #pragma unroll
    for (int i = 0; i < 8; i++) {
        int r = m0 + (ty << 3) + i;
        *(float4*)(out + (size_t)r * Dd + n0 + (tx << 2)) =
            make_float4(acc[i][0] + bv.x, acc[i][1] + bv.y,
                        acc[i][2] + bv.z, acc[i][3] + bv.w);
    }
}

// ---------------------------------------------------------------------------
// Launch
// ---------------------------------------------------------------------------
extern "C" void kernel_launch(void* const* d_in, const int* in_sizes, int n_in,
                              void* d_out, int out_size) {
    const float*         x      = (const float*)d_in[0];
    const float*         coords = (const float*)d_in[1];
    const unsigned char* mask   = (const unsigned char*)d_in[2];
    const float*         qkv_w  = (const float*)d_in[3];
    const float*         out_w  = (const float*)d_in[4];
    const float*         out_b  = (const float*)d_in[5];
    const float*         w1     = (const float*)d_in[6];
    const float*         b1     = (const float*)d_in[7];
    const float*         w2     = (const float*)d_in[8];
    const float*         b2     = (const float*)d_in[9];
    float*               out    = (float*)d_out;

    k_qkv    <<<dim3(12, 32),      256>>>(x, qkv_w);
    k_bias   <<<dim3(32, 32, Bb),  256>>>(coords, w1, b1, w2, b2);
    k_dots   <<<dim3(8, 8, 32),    256>>>();
    k_softmax<<<Bb * Hh * Nn,      256>>>(mask);
    k_av     <<<dim3(8, 32),       256>>>();
    k_out    <<<dim3(8, 32),       256>>>(out_w, out_b, out);
}

// round 7
// speedup vs baseline: 1.3660x; 1.1067x over previous
#include <cuda_runtime.h>
#include <math.h>

#define Bb   4
#define Nn   1024
#define Dd   512
#define Hh   8
#define DHh  64
#define HIDn 32
#define BKk  16

// Static scratch (allocation-free per harness rules)
__device__ float g_q[Bb*Hh*Nn*DHh];               // pre-scaled by dh^-0.5
__device__ float g_k[Bb*Hh*Nn*DHh];
__device__ float g_v[Bb*Hh*Nn*DHh];
__device__ float g_bias[(size_t)Bb*Hh*Nn*Nn];     // [B,H,N,N] additive bias
__device__ float g_att[Bb*Nn*Dd];                 // [B,N,D] attention output

// ---------------------------------------------------------------------------
// Split LDG/STS tile movers for double-buffered GEMMs (256 threads).
// ---------------------------------------------------------------------------
__device__ __forceinline__ void ldgT128(float4 r[2], const float* __restrict__ src,
                                        int ld, int tid) {
    #pragma unroll
    for (int it = 0; it < 2; it++) {
        int lin = tid + (it << 8);
        int m = lin >> 2, kq = (lin & 3) << 2;
        r[it] = *(const float4*)(src + (size_t)m * ld + kq);
    }
}
__device__ __forceinline__ void stsT128(float* dst, const float4 r[2], int tid) {
    #pragma unroll
    for (int it = 0; it < 2; it++) {
        int lin = tid + (it << 8);
        int m = lin >> 2, kq = (lin & 3) << 2;
        dst[(kq + 0) * 132 + m] = r[it].x;
        dst[(kq + 1) * 132 + m] = r[it].y;
        dst[(kq + 2) * 132 + m] = r[it].z;
        dst[(kq + 3) * 132 + m] = r[it].w;
    }
}
__device__ __forceinline__ void ldgN128(float4 r[2], const float* __restrict__ src,
                                        int ld, int tid) {
    #pragma unroll
    for (int it = 0; it < 2; it++) {
        int lin = tid + (it << 8);
        int k = lin >> 5, nq = (lin & 31) << 2;
        r[it] = *(const float4*)(src + (size_t)k * ld + nq);
    }
}
__device__ __forceinline__ void stsN128(float* dst, const float4 r[2], int tid) {
    #pragma unroll
    for (int it = 0; it < 2; it++) {
        int lin = tid + (it << 8);
        int k = lin >> 5, nq = (lin & 31) << 2;
        *(float4*)(dst + k * 132 + nq) = r[it];
    }
}
__device__ __forceinline__ void ldgN64(float4& r, const float* __restrict__ src,
                                       int ld, int tid) {
    int k = tid >> 4, nq = (tid & 15) << 2;
    r = *(const float4*)(src + (size_t)k * ld + nq);
}
__device__ __forceinline__ void stsN64(float* dst, const float4& r, int tid) {
    int k = tid >> 4, nq = (tid & 15) << 2;
    *(float4*)(dst + k * 68 + nq) = r;
}

__device__ __forceinline__ void mm8x8(const float* As, const float* Bs,
                                      float acc[8][8], int tx, int ty) {
    #pragma unroll
    for (int k = 0; k < BKk; k++) {
        float a[8], b[8];
        *(float4*)&a[0] = *(const float4*)(As + k * 132 + (ty << 3));
        *(float4*)&a[4] = *(const float4*)(As + k * 132 + (ty << 3) + 4);
        *(float4*)&b[0] = *(const float4*)(Bs + k * 132 + (tx << 3));
        *(float4*)&b[4] = *(const float4*)(Bs + k * 132 + (tx << 3) + 4);
        #pragma unroll
        for (int i = 0; i < 8; i++)
            #pragma unroll
            for (int j = 0; j < 8; j++)
                acc[i][j] = fmaf(a[i], b[j], acc[i][j]);
    }
}

__device__ __forceinline__ void mm8x4(const float* As, const float* Bs,
                                      float acc[8][4], int tx, int ty) {
    #pragma unroll
    for (int k = 0; k < BKk; k++) {
        float a[8], b[4];
        *(float4*)&a[0] = *(const float4*)(As + k * 132 + (ty << 3));
        *(float4*)&a[4] = *(const float4*)(As + k * 132 + (ty << 3) + 4);
        *(float4*)&b[0] = *(const float4*)(Bs + k * 68 + (tx << 2));
        #pragma unroll
        for (int i = 0; i < 8; i++)
            #pragma unroll
            for (int j = 0; j < 4; j++)
                acc[i][j] = fmaf(a[i], b[j], acc[i][j]);
    }
}

// ---------------------------------------------------------------------------
// K1: QKV projection (double-buffered). [4096,1536] = x @ qkv_w, scattered
// into g_q (x0.125), g_k, g_v as [B,H,N,dh].
// ---------------------------------------------------------------------------
__global__ __launch_bounds__(256, 2) void k_qkv(const float* __restrict__ X,
                                                const float* __restrict__ W) {
    __shared__ float As[BKk * 132];
    __shared__ float Bs[BKk * 132];
    int tid = threadIdx.x, tx = tid & 15, ty = tid >> 4;
    int n0 = blockIdx.x << 7, m0 = blockIdx.y << 7;
    float acc[8][8] = {};
    float4 ra[2], rb[2];
    ldgT128(ra, X + (size_t)m0 * Dd, Dd, tid);
    ldgN128(rb, W + n0, 3 * Dd, tid);
    for (int k0 = 0; k0 < Dd; k0 += BKk) {
        stsT128(As, ra, tid);
        stsN128(Bs, rb, tid);
        __syncthreads();
        if (k0 + BKk < Dd) {
            ldgT128(ra, X + (size_t)m0 * Dd + k0 + BKk, Dd, tid);
            ldgN128(rb, W + (size_t)(k0 + BKk) * (3 * Dd) + n0, 3 * Dd, tid);
        }
        mm8x8(As, Bs, acc, tx, ty);
        __syncthreads();
    }
    int c0  = n0 + (tx << 3);
    int sec = c0 >> 9;
    int d0  = c0 & 511;
    int h   = d0 >> 6, e = d0 & 63;
    float* dst = (sec == 0) ? g_q : (sec == 1) ? g_k : g_v;
    float  s   = (sec == 0) ? 0.125f : 1.0f;
    #pragma unroll
    for (int i = 0; i < 8; i++) {
        int r = m0 + (ty << 3) + i;
        int b = r >> 10, n = r & 1023;
        float* pd = dst + ((size_t)(b * Hh + h) * Nn + n) * DHh + e;
        *(float4*)pd       = make_float4(acc[i][0]*s, acc[i][1]*s, acc[i][2]*s, acc[i][3]*s);
        *(float4*)(pd + 4) = make_float4(acc[i][4]*s, acc[i][5]*s, acc[i][6]*s, acc[i][7]*s);
    }
}

// ---------------------------------------------------------------------------
// K2: relative-position bias MLP, once per (b,i,j) for all 8 heads.
// ---------------------------------------------------------------------------
__global__ __launch_bounds__(256) void k_bias(const float* __restrict__ coords,
                                              const float* __restrict__ w1,
                                              const float* __restrict__ b1,
                                              const float* __restrict__ w2,
                                              const float* __restrict__ b2) {
    __shared__ float sw1[3 * HIDn];
    __shared__ float sb1[HIDn];
    __shared__ float sw2[HIDn * Hh];
    __shared__ float sb2[Hh];
    __shared__ float ci[32][3];
    __shared__ float cj[32][3];

    int b  = blockIdx.z;
    int i0 = blockIdx.y << 5;
    int j0 = blockIdx.x << 5;
    int tid = threadIdx.x;

    if (tid < 96)  sw1[tid] = w1[tid];
    if (tid < 32)  sb1[tid] = b1[tid];
    sw2[tid] = w2[tid];
    if (tid < 8)   sb2[tid] = b2[tid];
    if (tid < 96) {
        int r = tid / 3, c = tid % 3;
        ci[r][c] = coords[((size_t)(b << 10) + i0 + r) * 3 + c];
    }
    if (tid >= 128 && tid < 224) {
        int t = tid - 128;
        int r = t / 3, c = t % 3;
        cj[r][c] = coords[((size_t)(b << 10) + j0 + r) * 3 + c];
    }
    __syncthreads();

    for (int p = tid; p < 1024; p += 256) {
        int i = p >> 5, j = p & 31;
        float dx = ci[i][0] - cj[j][0];
        float dy = ci[i][1] - cj[j][1];
        float dz = ci[i][2] - cj[j][2];
        float acc[Hh];
        #pragma unroll
        for (int h = 0; h < Hh; h++) acc[h] = sb2[h];
        #pragma unroll
        for (int m = 0; m < HIDn; m++) {
            float hs = fmaf(dx, sw1[m], fmaf(dy, sw1[32 + m], fmaf(dz, sw1[64 + m], sb1[m])));
            float g  = 0.5f * hs * (1.0f + erff(hs * 0.70710678118654752f));
            #pragma unroll
            for (int h = 0; h < Hh; h++) acc[h] = fmaf(g, sw2[m * Hh + h], acc[h]);
        }
        int gi = i0 + i, gj = j0 + j;
        #pragma unroll
        for (int h = 0; h < Hh; h++)
            g_bias[((size_t)((b * Hh + h) << 10) + gi) * Nn + gj] = acc[h];
    }
}

// ---------------------------------------------------------------------------
// K3: fused attention: S = Q@K^T + bias (mask), online softmax, O = P@V.
// One CTA = 128 query rows of one (b,h). j-tiles of 64. 256 threads,
// tx (&15) -> 4 j/e cols, ty (>>4) -> 8 i rows.
// Dynamic smem: Qs[64][132] + Ks[64][68] + Vs[64][68] + Ps[128][68... see layout
// ---------------------------------------------------------------------------
#define ATTN_SMEM ((64*132 + 64*68 + 64*68 + 128*68) * 4)

__global__ __launch_bounds__(256, 2) void k_attn(const unsigned char* __restrict__ mask) {
    extern __shared__ float fsm[];
    float* Qs = fsm;                 // [k=64][i=128] pitch 132 (transposed Q)
    float* Ks = Qs + 64 * 132;       // [k=64][j=64]  pitch 68  (transposed K)
    float* Vs = Ks + 64 * 68;        // [j=64][e=64]  pitch 68
    float* Ps = Vs + 64 * 68;        // [i=128][j=64] pitch 68

    int tid = threadIdx.x, tx = tid & 15, ty = tid >> 4;
    int bh = blockIdx.y, i0 = blockIdx.x << 7;
    int b = bh >> 3, h = bh & 7;

    const float* Q    = g_q + (size_t)bh * Nn * DHh;
    const float* Kg   = g_k + (size_t)bh * Nn * DHh;
    const float* Vg   = g_v + (size_t)bh * Nn * DHh;
    const float* Bias = g_bias + (size_t)bh * Nn * Nn;
    const unsigned char* mrow = mask + ((size_t)b << 10);

    // Load Q tile (128 x 64) transposed into Qs
    #pragma unroll
    for (int it = 0; it < 8; it++) {
        int lin = tid + (it << 8);
        int m = lin >> 4, kq = (lin & 15) << 2;
        float4 v = *(const float4*)(Q + (size_t)(i0 + m) * DHh + kq);
        Qs[(kq + 0) * 132 + m] = v.x;
        Qs[(kq + 1) * 132 + m] = v.y;
        Qs[(kq + 2) * 132 + m] = v.z;
        Qs[(kq + 3) * 132 + m] = v.w;
    }

    float m_i[8], l_i[8], o[8][4];
    #pragma unroll
    for (int i = 0; i < 8; i++) {
        m_i[i] = -1e30f; l_i[i] = 0.0f;
        #pragma unroll
        for (int j = 0; j < 4; j++) o[i][j] = 0.0f;
    }

    for (int j0 = 0; j0 < Nn; j0 += 64) {
        __syncthreads();   // previous PV done (and Qs stores on first iter)
        // Load K (transposed) and V tiles
        #pragma unroll
        for (int it = 0; it < 4; it++) {
            int lin = tid + (it << 8);
            int j = lin >> 4, kq = (lin & 15) << 2;
            float4 kv = *(const float4*)(Kg + (size_t)(j0 + j) * DHh + kq);
            Ks[(kq + 0) * 68 + j] = kv.x;
            Ks[(kq + 1) * 68 + j] = kv.y;
            Ks[(kq + 2) * 68 + j] = kv.z;
            Ks[(kq + 3) * 68 + j] = kv.w;
            *(float4*)(Vs + j * 68 + kq) = *(const float4*)(Vg + (size_t)(j0 + j) * DHh + kq);
        }
        __syncthreads();

        // S = Q @ K^T  (q pre-scaled)
        float s[8][4];
        #pragma unroll
        for (int i = 0; i < 8; i++)
            #pragma unroll
            for (int j = 0; j < 4; j++) s[i][j] = 0.0f;
        #pragma unroll
        for (int k = 0; k < 64; k++) {
            float a[8], bq[4];
            *(float4*)&a[0]  = *(const float4*)(Qs + k * 132 + (ty << 3));
            *(float4*)&a[4]  = *(const float4*)(Qs + k * 132 + (ty << 3) + 4);
            *(float4*)&bq[0] = *(const float4*)(Ks + k * 68 + (tx << 2));
            #pragma unroll
            for (int i = 0; i < 8; i++)
                #pragma unroll
                for (int j = 0; j < 4; j++)
                    s[i][j] = fmaf(a[i], bq[j], s[i][j]);
        }

        // + bias, mask
        uchar4 mk = *(const uchar4*)(mrow + j0 + (tx << 2));
        #pragma unroll
        for (int i = 0; i < 8; i++) {
            int gi = i0 + (ty << 3) + i;
            float4 bv = *(const float4*)(Bias + (size_t)gi * Nn + j0 + (tx << 2));
            s[i][0] += bv.x; s[i][1] += bv.y; s[i][2] += bv.z; s[i][3] += bv.w;
            if (mk.x) s[i][0] = -1e30f;
            if (mk.y) s[i][1] = -1e30f;
            if (mk.z) s[i][2] = -1e30f;
            if (mk.w) s[i][3] = -1e30f;
        }

        // online softmax update; write P to Ps[i][j]
        #pragma unroll
        for (int i = 0; i < 8; i++) {
            float mx = fmaxf(fmaxf(s[i][0], s[i][1]), fmaxf(s[i][2], s[i][3]));
            #pragma unroll
            for (int off = 8; off; off >>= 1)
                mx = fmaxf(mx, __shfl_xor_sync(0xFFFFFFFFu, mx, off));
            float mn = fmaxf(m_i[i], mx);
            float f  = __expf(m_i[i] - mn);
            m_i[i] = mn;
            float p0 = __expf(s[i][0] - mn);
            float p1 = __expf(s[i][1] - mn);
            float p2 = __expf(s[i][2] - mn);
            float p3 = __expf(s[i][3] - mn);
            l_i[i] = l_i[i] * f + (p0 + p1 + p2 + p3);
            o[i][0] *= f; o[i][1] *= f; o[i][2] *= f; o[i][3] *= f;
            int il = (ty << 3) + i;
            *(float4*)(Ps + il * 68 + (tx << 2)) = make_float4(p0, p1, p2, p3);
        }
        __syncthreads();

        // O += P @ V   (P broadcast loads, V vector loads)
        #pragma unroll
        for (int jg = 0; jg < 16; jg++) {
            float4 vv0 = *(const float4*)(Vs + (jg * 4 + 0) * 68 + (tx << 2));
            float4 vv1 = *(const float4*)(Vs + (jg * 4 + 1) * 68 + (tx << 2));
            float4 vv2 = *(const float4*)(Vs + (jg * 4 + 2) * 68 + (tx << 2));
            float4 vv3 = *(const float4*)(Vs + (jg * 4 + 3) * 68 + (tx << 2));
            #pragma unroll
            for (int i = 0; i < 8; i++) {
                float4 pv = *(const float4*)(Ps + ((ty << 3) + i) * 68 + (jg << 2));
                o[i][0] = fmaf(pv.x, vv0.x, o[i][0]);
                o[i][1] = fmaf(pv.x, vv0.y, o[i][1]);
                o[i][2] = fmaf(pv.x, vv0.z, o[i][2]);
                o[i][3] = fmaf(pv.x, vv0.w, o[i][3]);
                o[i][0] = fmaf(pv.y, vv1.x, o[i][0]);
                o[i][1] = fmaf(pv.y, vv1.y, o[i][1]);
                o[i][2] = fmaf(pv.y, vv1.z, o[i][2]);
                o[i][3] = fmaf(pv.y, vv1.w, o[i][3]);
                o[i][0] = fmaf(pv.z, vv2.x, o[i][0]);
                o[i][1] = fmaf(pv.z, vv2.y, o[i][1]);
                o[i][2] = fmaf(pv.z, vv2.z, o[i][2]);
                o[i][3] = fmaf(pv.z, vv2.w, o[i][3]);
                o[i][0] = fmaf(pv.w, vv3.x, o[i][0]);
                o[i][1] = fmaf(pv.w, vv3.y, o[i][1]);
                o[i][2] = fmaf(pv.w, vv3.z, o[i][2]);
                o[i][3] = fmaf(pv.w, vv3.w, o[i][3]);
            }
        }
    }

    // finalize: divide by row sum, write to g_att[b, i, h*64 + e]
    #pragma unroll
    for (int i = 0; i < 8; i++) {
        float lt = l_i[i];
        #pragma unroll
        for (int off = 8; off; off >>= 1)
            lt += __shfl_xor_sync(0xFFFFFFFFu, lt, off);
        float inv = __frcp_rn(lt);
        int gi = i0 + (ty << 3) + i;
        *(float4*)(g_att + ((size_t)(b << 10) + gi) * Dd + h * DHh + (tx << 2)) =
            make_float4(o[i][0] * inv, o[i][1] * inv, o[i][2] * inv, o[i][3] * inv);
    }
}

// ---------------------------------------------------------------------------
// K4: output projection (double-buffered). out = g_att @ out_w + out_b
// ---------------------------------------------------------------------------
__global__ __launch_bounds__(256, 2) void k_out(const float* __restrict__ W,
                                                const float* __restrict__ bias,
                                                float* __restrict__ out) {
    __shared__ float As[BKk * 132];
    __shared__ float Bs[BKk * 68];
    int tid = threadIdx.x, tx = tid & 15, ty = tid >> 4;
    int n0 = blockIdx.x << 6, m0 = blockIdx.y << 7;

    float acc[8][4] = {};
    float4 ra[2], rb;
    ldgT128(ra, g_att + (size_t)m0 * Dd, Dd, tid);
    ldgN64(rb, W + n0, Dd, tid);
    for (int k0 = 0; k0 < Dd; k0 += BKk) {
        stsT128(As, ra, tid);
        stsN64(Bs, rb, tid);
        __syncthreads();
        if (k0 + BKk < Dd) {
            ldgT128(ra, g_att + (size_t)m0 * Dd + k0 + BKk, Dd, tid);
            ldgN64(rb, W + (size_t)(k0 + BKk) * Dd + n0, Dd, tid);
        }
        mm8x4(As, Bs, acc, tx, ty);
        __syncthreads();
    }
    float4 bv = *(const float4*)(bias + n0 + (tx << 2));
    #pragma unroll
    for (int i = 0; i < 8; i++) {
        int r = m0 + (ty << 3) + i;
        *(float4*)(out + (size_t)r * Dd + n0 + (tx << 2)) =
            make_float4(acc[i][0] + bv.x, acc[i][1] + bv.y,
                        acc[i][2] + bv.z, acc[i][3] + bv.w);
    }
}

// ---------------------------------------------------------------------------
// Launch
// ---------------------------------------------------------------------------
extern "C" void kernel_launch(void* const* d_in, const int* in_sizes, int n_in,
                              void* d_out, int out_size) {
    const float*         x      = (const float*)d_in[0];
    const float*         coords = (const float*)d_in[1];
    const unsigned char* mask   = (const unsigned char*)d_in[2];
    const float*         qkv_w  = (const float*)d_in[3];
    const float*         out_w  = (const float*)d_in[4];
    const float*         out_b  = (const float*)d_in[5];
    const float*         w1     = (const float*)d_in[6];
    const float*         b1     = (const float*)d_in[7];
    const float*         w2     = (const float*)d_in[8];
    const float*         b2     = (const float*)d_in[9];
    float*               out    = (float*)d_out;

    static int attn_smem_set = 0;
    if (!attn_smem_set) {
        cudaFuncSetAttribute(k_attn, cudaFuncAttributeMaxDynamicSharedMemorySize, ATTN_SMEM);
        attn_smem_set = 1;
    }

    k_qkv <<<dim3(12, 32),     256>>>(x, qkv_w);
    k_bias<<<dim3(32, 32, Bb), 256>>>(coords, w1, b1, w2, b2);
    k_attn<<<dim3(8, 32),      256, ATTN_SMEM>>>(mask);
    k_out <<<dim3(8, 32),      256>>>(out_w, out_b, out);
}

// round 9
// speedup vs baseline: 1.5901x; 1.1640x over previous
#include <cuda_runtime.h>
#include <cuda_bf16.h>
#include <math.h>
#include <stdint.h>

#define Bb   4
#define Nn   1024
#define Dd   512
#define Hh   8
#define DHh  64
#define HIDn 32

// ---------------------------------------------------------------------------
// Static scratch (allocation-free per harness rules)
// ---------------------------------------------------------------------------
__device__ float g_q[Bb*Hh*Nn*DHh];               // pre-scaled by dh^-0.5
__device__ float g_k[Bb*Hh*Nn*DHh];
__device__ float g_v[Bb*Hh*Nn*DHh];
__device__ float g_bias[(size_t)Bb*Hh*Nn*Nn];     // [B,H,N,N] additive bias
__device__ float g_att[Bb*Nn*Dd];                 // [B,N,D] attention output

// bf16 hi/lo split operands for tensor-core GEMMs
__device__ __nv_bfloat16 g_xh[4096*512],  g_xl[4096*512];    // x            [M,K]
__device__ __nv_bfloat16 g_wth[1536*512], g_wtl[1536*512];   // qkv_w^T      [N,K]
__device__ __nv_bfloat16 g_ath[4096*512], g_atl[4096*512];   // att          [M,K]
__device__ __nv_bfloat16 g_owth[512*512], g_owtl[512*512];   // out_w^T      [N,K]

// ---------------------------------------------------------------------------
// mma.sync / ldmatrix helpers (baseline PTX, compile on plain sm_103)
// ---------------------------------------------------------------------------
__device__ __forceinline__ uint32_t smem_u32(const void* p) {
    uint32_t a;
    asm("{ .reg .u64 t; cvta.to.shared.u64 t, %1; cvt.u32.u64 %0, t; }" : "=r"(a) : "l"(p));
    return a;
}
__device__ __forceinline__ void ldsm4(uint32_t r[4], uint32_t addr) {
    asm volatile("ldmatrix.sync.aligned.m8n8.x4.shared.b16 {%0,%1,%2,%3}, [%4];"
        : "=r"(r[0]), "=r"(r[1]), "=r"(r[2]), "=r"(r[3]) : "r"(addr));
}
__device__ __forceinline__ void mma16816(float c[4], const uint32_t a[4], const uint32_t b[2]) {
    asm volatile("mma.sync.aligned.m16n8k16.row.col.f32.bf16.bf16.f32 "
        "{%0,%1,%2,%3}, {%4,%5,%6,%7}, {%8,%9}, {%0,%1,%2,%3};"
        : "+f"(c[0]), "+f"(c[1]), "+f"(c[2]), "+f"(c[3])
        : "r"(a[0]), "r"(a[1]), "r"(a[2]), "r"(a[3]), "r"(b[0]), "r"(b[1]));
}

// smem tile: 128 rows x 32 bf16 (one k-chunk), pitch 40 bf16 (80B) ->
// ldmatrix's 8 row addresses hit 8 distinct bank quads (conflict-free).
#define TP 40

// ---------------------------------------------------------------------------
// hi/lo bf16 split kernels
// ---------------------------------------------------------------------------
__device__ __forceinline__ void split_store4(float4 v, __nv_bfloat16* hi,
                                             __nv_bfloat16* lo, size_t i4) {
    float a[4] = {v.x, v.y, v.z, v.w};
    __nv_bfloat16 h[4], l[4];
    #pragma unroll
    for (int j = 0; j < 4; j++) {
        h[j] = __float2bfloat16_rn(a[j]);
        l[j] = __float2bfloat16_rn(a[j] - __bfloat162float(h[j]));
    }
    ((__nv_bfloat162*)hi)[2*i4]   = __halves2bfloat162(h[0], h[1]);
    ((__nv_bfloat162*)hi)[2*i4+1] = __halves2bfloat162(h[2], h[3]);
    ((__nv_bfloat162*)lo)[2*i4]   = __halves2bfloat162(l[0], l[1]);
    ((__nv_bfloat162*)lo)[2*i4+1] = __halves2bfloat162(l[2], l[3]);
}

__global__ __launch_bounds__(256) void k_split_x(const float4* __restrict__ src) {
    size_t i = (size_t)blockIdx.x * 256 + threadIdx.x;   // 524288 float4s
    split_store4(src[i], g_xh, g_xl, i);
}
__global__ __launch_bounds__(256) void k_split_att() {
    size_t i = (size_t)blockIdx.x * 256 + threadIdx.x;
    split_store4(((const float4*)g_att)[i], g_ath, g_atl, i);
}

// Transpose + split: src fp32 [K, N] -> dst bf16 [N, K]. which: 0=qkv_w, 1=out_w
__global__ void k_splitT(const float* __restrict__ src, int K, int N, int which) {
    __shared__ float ts[32][33];
    int kk = blockIdx.y * 32 + threadIdx.y;
    int nn = blockIdx.x * 32 + threadIdx.x;
    ts[threadIdx.y][threadIdx.x] = src[(size_t)kk * N + nn];
    __syncthreads();
    int on = blockIdx.x * 32 + threadIdx.y;
    int ok = blockIdx.y * 32 + threadIdx.x;
    float v = ts[threadIdx.x][threadIdx.y];
    __nv_bfloat16 h = __float2bfloat16_rn(v);
    __nv_bfloat16 l = __float2bfloat16_rn(v - __bfloat162float(h));
    __nv_bfloat16* hd = which ? g_owth : g_wth;
    __nv_bfloat16* ld = which ? g_owtl : g_wtl;
    hd[(size_t)on * K + ok] = h;
    ld[(size_t)on * K + ok] = l;
}

// ---------------------------------------------------------------------------
// Core bf16x3 HMMA mainloop. CTA tile 128(m) x 128(n), K=512 in chunks of 32.
// 8 warps: wy = wid>>2 (m 64-half), wx = wid&3 (n 32-quarter).
// acc[mt][nt][4]: 4 m16 tiles x 4 n8 tiles per warp.
// A sources are [M,512] row-major, B sources are [N,512] row-major (K-major).
// ---------------------------------------------------------------------------
struct SmemTiles {
    __nv_bfloat16 Ah[128 * TP];
    __nv_bfloat16 Al[128 * TP];
    __nv_bfloat16 Bh[128 * TP];
    __nv_bfloat16 Bl[128 * TP];
};

__device__ __forceinline__ void gmem_to_tile(__nv_bfloat16* dst,
                                             const __nv_bfloat16* __restrict__ src,
                                             int row0, int k0, int tid) {
    // 128 rows x 64B (32 bf16); 512 x 16B segments; 2 per thread
    #pragma unroll
    for (int i = 0; i < 2; i++) {
        int idx = tid + (i << 8);
        int rr = idx >> 2, sg = idx & 3;
        uint4 v = *(const uint4*)((const char*)src + ((size_t)(row0 + rr) * 512 + k0) * 2 + sg * 16);
        *(uint4*)((char*)dst + (rr * TP) * 2 + sg * 16) = v;
    }
}

__device__ __forceinline__ void mma_all(float acc[4][4][4],
                                        const uint32_t a[4][4],
                                        const uint32_t b[4][2]) {
    #pragma unroll
    for (int mt = 0; mt < 4; mt++)
        #pragma unroll
        for (int nt = 0; nt < 4; nt++)
            mma16816(acc[mt][nt], a[mt], b[nt]);
}

__device__ __forceinline__ void load_afrag(uint32_t a[4][4], uint32_t base_u32,
                                           int wyBase, int kb, int lane) {
    int r  = wyBase + (lane & 15);
    int kc = (kb << 4) + ((lane >> 4) << 3);
    uint32_t addr = base_u32 + (uint32_t)(r * TP + kc) * 2;
    #pragma unroll
    for (int mt = 0; mt < 4; mt++)
        ldsm4(a[mt], addr + mt * (16 * TP * 2));
}

__device__ __forceinline__ void load_bfrag(uint32_t b[4][2], uint32_t base_u32,
                                           int wxBase, int kb, int lane) {
    int n  = wxBase + (((lane >> 4) & 1) << 3) + (lane & 7);
    int kc = (kb << 4) + (((lane >> 3) & 1) << 3);
    uint32_t addr = base_u32 + (uint32_t)(n * TP + kc) * 2;
    #pragma unroll
    for (int np = 0; np < 2; np++) {
        uint32_t t4[4];
        ldsm4(t4, addr + np * (16 * TP * 2));
        b[np * 2 + 0][0] = t4[0]; b[np * 2 + 0][1] = t4[1];
        b[np * 2 + 1][0] = t4[2]; b[np * 2 + 1][1] = t4[3];
    }
}

// Runs the full K=512 mainloop, leaves result in acc.
__device__ __forceinline__ void hmma_mainloop(
    float acc[4][4][4], SmemTiles* sm,
    const __nv_bfloat16* Ah, const __nv_bfloat16* Al,
    const __nv_bfloat16* Bh, const __nv_bfloat16* Bl,
    int m0, int n0, int tid)
{
    int lane = tid & 31, wid = tid >> 5;
    int wyBase = (wid >> 2) * 64, wxBase = (wid & 3) * 32;
    uint32_t uAh = smem_u32(sm->Ah), uAl = smem_u32(sm->Al);
    uint32_t uBh = smem_u32(sm->Bh), uBl = smem_u32(sm->Bl);

    for (int k0 = 0; k0 < 512; k0 += 32) {
        gmem_to_tile(sm->Ah, Ah, m0, k0, tid);
        gmem_to_tile(sm->Al, Al, m0, k0, tid);
        gmem_to_tile(sm->Bh, Bh, n0, k0, tid);
        gmem_to_tile(sm->Bl, Bl, n0, k0, tid);
        __syncthreads();
        #pragma unroll
        for (int kb = 0; kb < 2; kb++) {
            uint32_t a[4][4], b[4][2];
            // order: (Ah,Bl) -> (Ah,Bh) -> (Al,Bh): one operand reload per step
            load_afrag(a, uAh, wyBase, kb, lane);
            load_bfrag(b, uBl, wxBase, kb, lane);
            mma_all(acc, a, b);
            load_bfrag(b, uBh, wxBase, kb, lane);
            mma_all(acc, a, b);
            load_afrag(a, uAl, wyBase, kb, lane);
            mma_all(acc, a, b);
        }
        __syncthreads();
    }
}

// ---------------------------------------------------------------------------
// K1: QKV projection on HMMA. C = x @ qkv_w, scattered into g_q(x0.125)/g_k/g_v.
// ---------------------------------------------------------------------------
__global__ __launch_bounds__(256, 2) void k_qkv_mma() {
    __shared__ SmemTiles sm;
    int tid = threadIdx.x;
    int n0 = blockIdx.x << 7, m0 = blockIdx.y << 7;

    float acc[4][4][4];
    #pragma unroll
    for (int mt = 0; mt < 4; mt++)
        #pragma unroll
        for (int nt = 0; nt < 4; nt++)
            acc[mt][nt][0] = acc[mt][nt][1] = acc[mt][nt][2] = acc[mt][nt][3] = 0.0f;

    hmma_mainloop(acc, &sm, g_xh, g_xl, g_wth, g_wtl, m0, n0, tid);

    int lane = tid & 31, wid = tid >> 5;
    int wyBase = (wid >> 2) * 64, wxBase = (wid & 3) * 32;
    int g = lane >> 2, tig = lane & 3;

    int sec = n0 >> 9;                       // constant per CTA
    float s = (sec == 0) ? 0.125f : 1.0f;
    float* dst = (sec == 0) ? g_q : (sec == 1) ? g_k : g_v;

    #pragma unroll
    for (int mt = 0; mt < 4; mt++) {
        #pragma unroll
        for (int nt = 0; nt < 4; nt++) {
            int col = n0 + wxBase + (nt << 3) + (tig << 1);
            int h = (col & 511) >> 6, e = col & 63;
            #pragma unroll
            for (int half = 0; half < 2; half++) {
                int row = m0 + wyBase + (mt << 4) + g + (half << 3);
                int b = row >> 10, n = row & 1023;
                float* pd = dst + ((size_t)((b << 3) + h) * Nn + n) * DHh + e;
                float2 v = make_float2(acc[mt][nt][half * 2] * s,
                                       acc[mt][nt][half * 2 + 1] * s);
                *(float2*)pd = v;
            }
        }
    }
}

// ---------------------------------------------------------------------------
// K4: output projection on HMMA. out = att @ out_w + out_b
// ---------------------------------------------------------------------------
__global__ __launch_bounds__(256, 2) void k_out_mma(const float* __restrict__ bias,
                                                    float* __restrict__ out) {
    __shared__ SmemTiles sm;
    int tid = threadIdx.x;
    int n0 = blockIdx.x << 7, m0 = blockIdx.y << 7;

    float acc[4][4][4];
    #pragma unroll
    for (int mt = 0; mt < 4; mt++)
        #pragma unroll
        for (int nt = 0; nt < 4; nt++)
            acc[mt][nt][0] = acc[mt][nt][1] = acc[mt][nt][2] = acc[mt][nt][3] = 0.0f;

    hmma_mainloop(acc, &sm, g_ath, g_atl, g_owth, g_owtl, m0, n0, tid);

    int lane = tid & 31, wid = tid >> 5;
    int wyBase = (wid >> 2) * 64, wxBase = (wid & 3) * 32;
    int g = lane >> 2, tig = lane & 3;

    #pragma unroll
    for (int mt = 0; mt < 4; mt++) {
        #pragma unroll
        for (int nt = 0; nt < 4; nt++) {
            int col = n0 + wxBase + (nt << 3) + (tig << 1);
            float2 bv = *(const float2*)(bias + col);
            #pragma unroll
            for (int half = 0; half < 2; half++) {
                int row = m0 + wyBase + (mt << 4) + g + (half << 3);
                *(float2*)(out + (size_t)row * Dd + col) =
                    make_float2(acc[mt][nt][half * 2] + bv.x,
                                acc[mt][nt][half * 2 + 1] + bv.y);
            }
        }
    }
}

// ---------------------------------------------------------------------------
// K2: relative-position bias MLP, once per (b,i,j) for all 8 heads.
// ---------------------------------------------------------------------------
__global__ __launch_bounds__(256) void k_bias(const float* __restrict__ coords,
                                              const float* __restrict__ w1,
                                              const float* __restrict__ b1,
                                              const float* __restrict__ w2,
                                              const float* __restrict__ b2) {
    __shared__ float sw1[3 * HIDn];
    __shared__ float sb1[HIDn];
    __shared__ float sw2[HIDn * Hh];
    __shared__ float sb2[Hh];
    __shared__ float ci[32][3];
    __shared__ float cj[32][3];

    int b  = blockIdx.z;
    int i0 = blockIdx.y << 5;
    int j0 = blockIdx.x << 5;
    int tid = threadIdx.x;

    if (tid < 96)  sw1[tid] = w1[tid];
    if (tid < 32)  sb1[tid] = b1[tid];
    sw2[tid] = w2[tid];
    if (tid < 8)   sb2[tid] = b2[tid];
    if (tid < 96) {
        int r = tid / 3, c = tid % 3;
        ci[r][c] = coords[((size_t)(b << 10) + i0 + r) * 3 + c];
    }
    if (tid >= 128 && tid < 224) {
        int t = tid - 128;
        int r = t / 3, c = t % 3;
        cj[r][c] = coords[((size_t)(b << 10) + j0 + r) * 3 + c];
    }
    __syncthreads();

    for (int p = tid; p < 1024; p += 256) {
        int i = p >> 5, j = p & 31;
        float dx = ci[i][0] - cj[j][0];
        float dy = ci[i][1] - cj[j][1];
        float dz = ci[i][2] - cj[j][2];
        float acc[Hh];
        #pragma unroll
        for (int h = 0; h < Hh; h++) acc[h] = sb2[h];
        #pragma unroll
        for (int m = 0; m < HIDn; m++) {
            float hs = fmaf(dx, sw1[m], fmaf(dy, sw1[32 + m], fmaf(dz, sw1[64 + m], sb1[m])));
            float g  = 0.5f * hs * (1.0f + erff(hs * 0.70710678118654752f));
            #pragma unroll
            for (int h = 0; h < Hh; h++) acc[h] = fmaf(g, sw2[m * Hh + h], acc[h]);
        }
        int gi = i0 + i, gj = j0 + j;
        #pragma unroll
        for (int h = 0; h < Hh; h++)
            g_bias[((size_t)((b * Hh + h) << 10) + gi) * Nn + gj] = acc[h];
    }
}

// ---------------------------------------------------------------------------
// K3: fused attention: S = Q@K^T + bias (mask), online softmax, O = P@V.
// ---------------------------------------------------------------------------
#define ATTN_SMEM ((64*132 + 64*68 + 64*68 + 128*68) * 4)

__global__ __launch_bounds__(256, 2) void k_attn(const unsigned char* __restrict__ mask) {
    extern __shared__ float fsm[];
    float* Qs = fsm;                 // [k=64][i=128] pitch 132 (transposed Q)
    float* Ks = Qs + 64 * 132;       // [k=64][j=64]  pitch 68  (transposed K)
    float* Vs = Ks + 64 * 68;        // [j=64][e=64]  pitch 68
    float* Ps = Vs + 64 * 68;        // [i=128][j=64] pitch 68

    int tid = threadIdx.x, tx = tid & 15, ty = tid >> 4;
    int bh = blockIdx.y, i0 = blockIdx.x << 7;
    int b = bh >> 3, h = bh & 7;

    const float* Q    = g_q + (size_t)bh * Nn * DHh;
    const float* Kg   = g_k + (size_t)bh * Nn * DHh;
    const float* Vg   = g_v + (size_t)bh * Nn * DHh;
    const float* Bias = g_bias + (size_t)bh * Nn * Nn;
    const unsigned char* mrow = mask + ((size_t)b << 10);

    #pragma unroll
    for (int it = 0; it < 8; it++) {
        int lin = tid + (it << 8);
        int m = lin >> 4, kq = (lin & 15) << 2;
        float4 v = *(const float4*)(Q + (size_t)(i0 + m) * DHh + kq);
        Qs[(kq + 0) * 132 + m] = v.x;
        Qs[(kq + 1) * 132 + m] = v.y;
        Qs[(kq + 2) * 132 + m] = v.z;
        Qs[(kq + 3) * 132 + m] = v.w;
    }

    float m_i[8], l_i[8], o[8][4];
    #pragma unroll
    for (int i = 0; i < 8; i++) {
        m_i[i] = -1e30f; l_i[i] = 0.0f;
        #pragma unroll
        for (int j = 0; j < 4; j++) o[i][j] = 0.0f;
    }

    for (int j0 = 0; j0 < Nn; j0 += 64) {
        __syncthreads();
        #pragma unroll
        for (int it = 0; it < 4; it++) {
            int lin = tid + (it << 8);
            int j = lin >> 4, kq = (lin & 15) << 2;
            float4 kv = *(const float4*)(Kg + (size_t)(j0 + j) * DHh + kq);
            Ks[(kq + 0) * 68 + j] = kv.x;
            Ks[(kq + 1) * 68 + j] = kv.y;
            Ks[(kq + 2) * 68 + j] = kv.z;
            Ks[(kq + 3) * 68 + j] = kv.w;
            *(float4*)(Vs + j * 68 + kq) = *(const float4*)(Vg + (size_t)(j0 + j) * DHh + kq);
        }
        __syncthreads();

        float s[8][4];
        #pragma unroll
        for (int i = 0; i < 8; i++)
            #pragma unroll
            for (int j = 0; j < 4; j++) s[i][j] = 0.0f;
        #pragma unroll
        for (int k = 0; k < 64; k++) {
            float a[8], bq[4];
            *(float4*)&a[0]  = *(const float4*)(Qs + k * 132 + (ty << 3));
            *(float4*)&a[4]  = *(const float4*)(Qs + k * 132 + (ty << 3) + 4);
            *(float4*)&bq[0] = *(const float4*)(Ks + k * 68 + (tx << 2));
            #pragma unroll
            for (int i = 0; i < 8; i++)
                #pragma unroll
                for (int j = 0; j < 4; j++)
                    s[i][j] = fmaf(a[i], bq[j], s[i][j]);
        }

        uchar4 mk = *(const uchar4*)(mrow + j0 + (tx << 2));
        #pragma unroll
        for (int i = 0; i < 8; i++) {
            int gi = i0 + (ty << 3) + i;
            float4 bv = *(const float4*)(Bias + (size_t)gi * Nn + j0 + (tx << 2));
            s[i][0] += bv.x; s[i][1] += bv.y; s[i][2] += bv.z; s[i][3] += bv.w;
            if (mk.x) s[i][0] = -1e30f;
            if (mk.y) s[i][1] = -1e30f;
            if (mk.z) s[i][2] = -1e30f;
            if (mk.w) s[i][3] = -1e30f;
        }

        #pragma unroll
        for (int i = 0; i < 8; i++) {
            float mx = fmaxf(fmaxf(s[i][0], s[i][1]), fmaxf(s[i][2], s[i][3]));
            #pragma unroll
            for (int off = 8; off; off >>= 1)
                mx = fmaxf(mx, __shfl_xor_sync(0xFFFFFFFFu, mx, off));
            float mn = fmaxf(m_i[i], mx);
            float f  = __expf(m_i[i] - mn);
            m_i[i] = mn;
            float p0 = __expf(s[i][0] - mn);
            float p1 = __expf(s[i][1] - mn);
            float p2 = __expf(s[i][2] - mn);
            float p3 = __expf(s[i][3] - mn);
            l_i[i] = l_i[i] * f + (p0 + p1 + p2 + p3);
            o[i][0] *= f; o[i][1] *= f; o[i][2] *= f; o[i][3] *= f;
            int il = (ty << 3) + i;
            *(float4*)(Ps + il * 68 + (tx << 2)) = make_float4(p0, p1, p2, p3);
        }
        __syncthreads();

        #pragma unroll
        for (int jg = 0; jg < 16; jg++) {
            float4 vv0 = *(const float4*)(Vs + (jg * 4 + 0) * 68 + (tx << 2));
            float4 vv1 = *(const float4*)(Vs + (jg * 4 + 1) * 68 + (tx << 2));
            float4 vv2 = *(const float4*)(Vs + (jg * 4 + 2) * 68 + (tx << 2));
            float4 vv3 = *(const float4*)(Vs + (jg * 4 + 3) * 68 + (tx << 2));
            #pragma unroll
            for (int i = 0; i < 8; i++) {
                float4 pv = *(const float4*)(Ps + ((ty << 3) + i) * 68 + (jg << 2));
                o[i][0] = fmaf(pv.x, vv0.x, o[i][0]);
                o[i][1] = fmaf(pv.x, vv0.y, o[i][1]);
                o[i][2] = fmaf(pv.x, vv0.z, o[i][2]);
                o[i][3] = fmaf(pv.x, vv0.w, o[i][3]);
                o[i][0] = fmaf(pv.y, vv1.x, o[i][0]);
                o[i][1] = fmaf(pv.y, vv1.y, o[i][1]);
                o[i][2] = fmaf(pv.y, vv1.z, o[i][2]);
                o[i][3] = fmaf(pv.y, vv1.w, o[i][3]);
                o[i][0] = fmaf(pv.z, vv2.x, o[i][0]);
                o[i][1] = fmaf(pv.z, vv2.y, o[i][1]);
                o[i][2] = fmaf(pv.z, vv2.z, o[i][2]);
                o[i][3] = fmaf(pv.z, vv2.w, o[i][3]);
                o[i][0] = fmaf(pv.w, vv3.x, o[i][0]);
                o[i][1] = fmaf(pv.w, vv3.y, o[i][1]);
                o[i][2] = fmaf(pv.w, vv3.z, o[i][2]);
                o[i][3] = fmaf(pv.w, vv3.w, o[i][3]);
            }
        }
    }

    #pragma unroll
    for (int i = 0; i < 8; i++) {
        float lt = l_i[i];
        #pragma unroll
        for (int off = 8; off; off >>= 1)
            lt += __shfl_xor_sync(0xFFFFFFFFu, lt, off);
        float inv = __frcp_rn(lt);
        int gi = i0 + (ty << 3) + i;
        *(float4*)(g_att + ((size_t)(b << 10) + gi) * Dd + h * DHh + (tx << 2)) =
            make_float4(o[i][0] * inv, o[i][1] * inv, o[i][2] * inv, o[i][3] * inv);
    }
}

// ---------------------------------------------------------------------------
// Launch
// ---------------------------------------------------------------------------
extern "C" void kernel_launch(void* const* d_in, const int* in_sizes, int n_in,
                              void* d_out, int out_size) {
    const float*         x      = (const float*)d_in[0];
    const float*         coords = (const float*)d_in[1];
    const unsigned char* mask   = (const unsigned char*)d_in[2];
    const float*         qkv_w  = (const float*)d_in[3];
    const float*         out_w  = (const float*)d_in[4];
    const float*         out_b  = (const float*)d_in[5];
    const float*         w1     = (const float*)d_in[6];
    const float*         b1     = (const float*)d_in[7];
    const float*         w2     = (const float*)d_in[8];
    const float*         b2     = (const float*)d_in[9];
    float*               out    = (float*)d_out;

    static int attrs_set = 0;
    if (!attrs_set) {
        cudaFuncSetAttribute(k_attn, cudaFuncAttributeMaxDynamicSharedMemorySize, ATTN_SMEM);
        attrs_set = 1;
    }

    k_split_x  <<<2048, 256>>>((const float4*)x);
    k_splitT   <<<dim3(48, 16), dim3(32, 32)>>>(qkv_w, Dd, 3 * Dd, 0);
    k_qkv_mma  <<<dim3(12, 32), 256>>>();
    k_bias     <<<dim3(32, 32, Bb), 256>>>(coords, w1, b1, w2, b2);
    k_attn     <<<dim3(8, 32), 256, ATTN_SMEM>>>(mask);
    k_split_att<<<2048, 256>>>();
    k_splitT   <<<dim3(16, 16), dim3(32, 32)>>>(out_w, Dd, Dd, 1);
    k_out_mma  <<<dim3(4, 32), 256>>>(out_b, out);
}